// round 3
// baseline (speedup 1.0000x reference)
#include <cuda_runtime.h>
#include <cuda_bf16.h>
#include <math.h>

#define BATCH 64
#define TLEN  512
#define DIM   512

// -------- device scratch (static; no allocations allowed) --------
__device__ float g_x[3][TLEN * BATCH * DIM];   // time-major [t][b][j] projections z,r,h
__device__ float g_h[BATCH * DIM];
__device__ float g_rh[BATCH * DIM];
__device__ float g_zb[BATCH * DIM];
__device__ unsigned int g_count;

// -------- grid barrier (all blocks resident: grid=128 <= 148 SMs, 1 blk/SM) ----
__device__ __forceinline__ void grid_barrier(unsigned int target, int nblocks) {
    __threadfence();            // publish this thread's global writes to L2
    __syncthreads();
    if (threadIdx.x == 0) {
        atomicAdd(&g_count, 1u);
        while (*((volatile unsigned int*)&g_count) < target) { }
    }
    __syncthreads();
    // cross-block data after this point is read with __ldcg (L2-direct),
    // so no L1 invalidation fence is required here.
    (void)nblocks;
}

__global__ void init_k() { g_count = 0u; }

// =================================================================
// Phase 1: input projections  X[32768,512] @ W[512,512] (x3) + bias
// BM=128, BN=64, BK=16, 256 threads, thread tile 8x4
// =================================================================
__global__ __launch_bounds__(256) void proj_kernel(
    const float* __restrict__ X,
    const float* __restrict__ Wz, const float* __restrict__ Wr, const float* __restrict__ Wh,
    const float* __restrict__ bz, const float* __restrict__ br, const float* __restrict__ bh)
{
    __shared__ float As[16 * 132];   // A transposed: As[k][m], padded row 132
    __shared__ float Bs[16 * 68];    // Bs[k][n], padded row 68

    const int mat = blockIdx.z;
    const float* W    = (mat == 0) ? Wz : ((mat == 1) ? Wr : Wh);
    const float* bias = (mat == 0) ? bz : ((mat == 1) ? br : bh);
    float* dst = &g_x[mat][0];

    const int m0 = blockIdx.y * 128;
    const int n0 = blockIdx.x * 64;
    const int tid = threadIdx.x;
    const int tx = tid & 15;        // n-group (4 cols)
    const int ty = tid >> 4;        // m-group (8 rows)

    float acc[8][4];
#pragma unroll
    for (int i = 0; i < 8; ++i)
#pragma unroll
        for (int j = 0; j < 4; ++j) acc[i][j] = 0.f;

    for (int kt = 0; kt < 512; kt += 16) {
        // load A tile 128x16 (transposed into smem)
#pragma unroll
        for (int ii = 0; ii < 2; ++ii) {
            int i = tid + ii * 256;            // 0..511 (float4 index)
            int r = i >> 2;                    // row in tile 0..127
            int cq = i & 3;                    // which float4 in the 16-k row
            float4 v = *(const float4*)&X[(m0 + r) * 512 + kt + cq * 4];
            As[(cq * 4 + 0) * 132 + r] = v.x;
            As[(cq * 4 + 1) * 132 + r] = v.y;
            As[(cq * 4 + 2) * 132 + r] = v.z;
            As[(cq * 4 + 3) * 132 + r] = v.w;
        }
        // load B tile 16x64
        {
            int r = tid >> 4;                  // k row 0..15
            int c = (tid & 15) * 4;            // col
            float4 v = *(const float4*)&W[(kt + r) * 512 + n0 + c];
            *(float4*)&Bs[r * 68 + c] = v;
        }
        __syncthreads();
#pragma unroll
        for (int k = 0; k < 16; ++k) {
            float4 a0 = *(const float4*)&As[k * 132 + ty * 8];
            float4 a1 = *(const float4*)&As[k * 132 + ty * 8 + 4];
            float4 bv = *(const float4*)&Bs[k * 68 + tx * 4];
            float a[8] = {a0.x, a0.y, a0.z, a0.w, a1.x, a1.y, a1.z, a1.w};
            float bb[4] = {bv.x, bv.y, bv.z, bv.w};
#pragma unroll
            for (int im = 0; im < 8; ++im)
#pragma unroll
                for (int ij = 0; ij < 4; ++ij)
                    acc[im][ij] = fmaf(a[im], bb[ij], acc[im][ij]);
        }
        __syncthreads();
    }

    float4 bv = *(const float4*)&bias[n0 + tx * 4];
#pragma unroll
    for (int im = 0; im < 8; ++im) {
        int m = m0 + ty * 8 + im;
        int t = m & 511;         // X is [B,T,D]: m = b*T + t
        int b = m >> 9;
        float4 o;
        o.x = acc[im][0] + bv.x;
        o.y = acc[im][1] + bv.y;
        o.z = acc[im][2] + bv.z;
        o.w = acc[im][3] + bv.w;
        *(float4*)&dst[(t * 64 + b) * 512 + n0 + tx * 4] = o;  // time-major
    }
}

// =================================================================
// Phase 2: persistent GRU recurrence. 128 blocks x 256 threads.
// Per step: [A] z|r matmul (8 cols/block over 1024 cols) + sigmoid,
//           barrier, [B] U_h matmul (4 cols/block) + tanh + update, barrier.
// Intra-block split-K: 8 warps each own 64 of K=512; smem reduction.
// =================================================================
#define SMEM_FLOATS (512*68 + 512*8 + 512*4 + 256*16)

__global__ __launch_bounds__(256) void gru_kernel(
    const float* __restrict__ Uz, const float* __restrict__ Ur, const float* __restrict__ Uh,
    const int* __restrict__ mask, float* __restrict__ out)
{
    extern __shared__ float sm[];
    float* h_s  = sm;                       // [512][68] transposed state (h or r*h)
    float* Ua_s = sm + 512 * 68;            // [512][8]  U_z or U_r slice (persistent)
    float* Ub_s = Ua_s + 512 * 8;           // [512][4]  U_h slice (persistent)
    float* red  = Ub_s + 512 * 4;           // [256][16] split-K reduction buffer

    const int tid  = threadIdx.x;
    const int jblk = blockIdx.x;            // 0..127
    const int nb   = gridDim.x;
    const bool isZ = (jblk < 64);
    const int jbase8 = (isZ ? jblk : jblk - 64) * 8;  // z|r column base
    const int jbase4 = jblk * 4;                      // U_h column base

    // ---- stage U slices once (constant across all 512 steps) ----
    {
        const float* Usel = isZ ? Uz : Ur;
        for (int i = tid; i < 1024; i += 256) {       // 512 rows x 2 float4
            int r = i >> 1, c = (i & 1) * 4;
            float4 v = *(const float4*)&Usel[r * 512 + jbase8 + c];
            *(float4*)&Ua_s[r * 8 + c] = v;
        }
        for (int i = tid; i < 512; i += 256) {
            float4 v = *(const float4*)&Uh[i * 512 + jbase4];
            *(float4*)&Ub_s[i * 4] = v;
        }
    }

    // ---- zero h (deterministic per launch / graph replay) ----
    g_h[jblk * 256 + tid] = 0.f;

    unsigned int barno = 0;
    grid_barrier(++barno * nb, nb);

    const int kc = tid >> 5;                // warp id = K chunk (64 k each)
    const int jg = (tid >> 4) & 1;
    const int bg = tid & 15;
    const int b0 = bg * 4;
    const int k0 = kc * 64;
    const int jg4 = jg * 4;
    const int jg2 = jg * 2;

    for (int t = 0; t < TLEN; ++t) {
        // =================== Phase A: z and r ===================
        // stage h (transposed) into smem; L2-direct reads for freshness
        for (int i = tid; i < 8192; i += 256) {
            int b = i >> 7, kq = i & 127;
            float4 v = __ldcg((const float4*)(g_h + b * 512 + kq * 4));
            int k = kq * 4;
            h_s[(k + 0) * 68 + b] = v.x;
            h_s[(k + 1) * 68 + b] = v.y;
            h_s[(k + 2) * 68 + b] = v.z;
            h_s[(k + 3) * 68 + b] = v.w;
        }
        __syncthreads();

        float acc[4][4];
#pragma unroll
        for (int i = 0; i < 4; ++i)
#pragma unroll
            for (int j = 0; j < 4; ++j) acc[i][j] = 0.f;

#pragma unroll 4
        for (int k = k0; k < k0 + 64; ++k) {
            float4 hv = *(const float4*)(h_s + k * 68 + b0);
            float4 uv = *(const float4*)(Ua_s + k * 8 + jg4);
            float a[4] = {hv.x, hv.y, hv.z, hv.w};
            float u[4] = {uv.x, uv.y, uv.z, uv.w};
#pragma unroll
            for (int ib = 0; ib < 4; ++ib)
#pragma unroll
                for (int ij = 0; ij < 4; ++ij)
                    acc[ib][ij] = fmaf(a[ib], u[ij], acc[ib][ij]);
        }

#pragma unroll
        for (int ib = 0; ib < 4; ++ib)
#pragma unroll
            for (int ij = 0; ij < 4; ++ij)
                red[tid * 16 + ib * 4 + ij] = acc[ib][ij];
        __syncthreads();

        {
            const float* xarr = isZ ? &g_x[0][0] : &g_x[1][0];
#pragma unroll
            for (int q = 0; q < 2; ++q) {
                int o = tid * 2 + q;           // 512 outputs
                int slot = o >> 4, i = o & 15;
                float s = 0.f;
#pragma unroll
                for (int c = 0; c < 8; ++c) s += red[(c * 32 + slot) * 16 + i];
                int b  = (slot & 15) * 4 + (i >> 2);
                int jl = ((slot >> 4) & 1) * 4 + (i & 3);
                int j  = jbase8 + jl;
                float v = xarr[t * 32768 + b * 512 + j] + s;
                float sg = 1.f / (1.f + __expf(-v));
                if (isZ) g_zb[b * 512 + j] = sg;
                else     g_rh[b * 512 + j] = sg * h_s[j * 68 + b];
            }
        }
        grid_barrier(++barno * nb, nb);

        // =================== Phase B: candidate + update ===================
        for (int i = tid; i < 8192; i += 256) {
            int b = i >> 7, kq = i & 127;
            float4 v = __ldcg((const float4*)(g_rh + b * 512 + kq * 4));
            int k = kq * 4;
            h_s[(k + 0) * 68 + b] = v.x;
            h_s[(k + 1) * 68 + b] = v.y;
            h_s[(k + 2) * 68 + b] = v.z;
            h_s[(k + 3) * 68 + b] = v.w;
        }
        __syncthreads();

        float acc2[4][2];
#pragma unroll
        for (int i = 0; i < 4; ++i) { acc2[i][0] = 0.f; acc2[i][1] = 0.f; }

#pragma unroll 4
        for (int k = k0; k < k0 + 64; ++k) {
            float4 hv = *(const float4*)(h_s + k * 68 + b0);
            float2 uv = *(const float2*)(Ub_s + k * 4 + jg2);
            float a[4] = {hv.x, hv.y, hv.z, hv.w};
#pragma unroll
            for (int ib = 0; ib < 4; ++ib) {
                acc2[ib][0] = fmaf(a[ib], uv.x, acc2[ib][0]);
                acc2[ib][1] = fmaf(a[ib], uv.y, acc2[ib][1]);
            }
        }

#pragma unroll
        for (int ib = 0; ib < 4; ++ib) {
            red[tid * 8 + ib * 2 + 0] = acc2[ib][0];
            red[tid * 8 + ib * 2 + 1] = acc2[ib][1];
        }
        __syncthreads();

        {
            int o = tid;                       // 256 outputs
            int slot = o >> 3, i = o & 7;
            float s = 0.f;
#pragma unroll
            for (int c = 0; c < 8; ++c) s += red[(c * 32 + slot) * 8 + i];
            int b  = (slot & 15) * 4 + (i >> 1);
            int jl = ((slot >> 4) & 1) * 2 + (i & 1);
            int j  = jbase4 + jl;
            float hh   = tanhf(g_x[2][t * 32768 + b * 512 + j] + s);
            float z    = __ldcg(g_zb + b * 512 + j);
            float hold = __ldcg(g_h + b * 512 + j);
            float hn   = z * hold + (1.f - z) * hh;
            float res  = (mask[b * 512 + t] > 0) ? hn : hold;
            g_h[b * 512 + j] = res;
            if (t == TLEN - 1) out[b * 512 + j] = res;
        }
        grid_barrier(++barno * nb, nb);
    }
}

// =================================================================
extern "C" void kernel_launch(void* const* d_in, const int* in_sizes, int n_in,
                              void* d_out, int out_size) {
    (void)in_sizes; (void)n_in; (void)out_size;
    const float* X    = (const float*)d_in[0];
    const int*   mask = (const int*)  d_in[1];
    const float* Wz   = (const float*)d_in[2];
    const float* Uz   = (const float*)d_in[3];
    const float* bz   = (const float*)d_in[4];
    const float* Wr   = (const float*)d_in[5];
    const float* Ur   = (const float*)d_in[6];
    const float* br   = (const float*)d_in[7];
    const float* Wh   = (const float*)d_in[8];
    const float* Uh   = (const float*)d_in[9];
    const float* bh   = (const float*)d_in[10];
    float* out = (float*)d_out;

    const int smem_bytes = SMEM_FLOATS * (int)sizeof(float);   // 180224
    cudaFuncSetAttribute(gru_kernel, cudaFuncAttributeMaxDynamicSharedMemorySize, smem_bytes);

    init_k<<<1, 1>>>();
    proj_kernel<<<dim3(8, 256, 3), 256>>>(X, Wz, Wr, Wh, bz, br, bh);
    gru_kernel<<<128, 256, smem_bytes>>>(Uz, Ur, Uh, mask, out);
}

// round 4
// speedup vs baseline: 1.6707x; 1.6707x over previous
#include <cuda_runtime.h>
#include <cuda_bf16.h>
#include <math.h>

#define BATCH 64
#define TLEN  512
#define DIM   512

// -------- device scratch (static; no allocations allowed) --------
__device__ float g_x[3][TLEN * BATCH * DIM];   // [gate][t][b][j] projections z,r,h
__device__ float g_hT[DIM * BATCH];            // transposed state: [j][b]
__device__ float g_rhT[DIM * BATCH];           // [j][b]
__device__ float g_zT[DIM * BATCH];            // [j][b]
__device__ unsigned int g_count;

// -------- grid barrier (128 blocks, 1 per SM, all resident) --------
__device__ __forceinline__ void grid_barrier(unsigned int target) {
    __threadfence();            // publish global writes to L2
    __syncthreads();
    if (threadIdx.x == 0) {
        atomicAdd(&g_count, 1u);
        while (*((volatile unsigned int*)&g_count) < target) { }
    }
    __syncthreads();
    // cross-block data is read with __ldcg (L2-direct), no L1 inval needed
}

// =================================================================
// Phase 1: input projections  X[32768,512] @ W[512,512] (x3) + bias
// BM=128, BN=64, BK=16, 256 threads, thread tile 8x4
// =================================================================
__global__ __launch_bounds__(256) void proj_kernel(
    const float* __restrict__ X,
    const float* __restrict__ Wz, const float* __restrict__ Wr, const float* __restrict__ Wh,
    const float* __restrict__ bz, const float* __restrict__ br, const float* __restrict__ bh)
{
    __shared__ float As[16 * 132];   // A transposed: As[k][m], padded row 132
    __shared__ float Bs[16 * 68];    // Bs[k][n], padded row 68

    if (threadIdx.x == 0 && blockIdx.x == 0 && blockIdx.y == 0 && blockIdx.z == 0)
        g_count = 0u;                // reset barrier counter for the gru kernel

    const int mat = blockIdx.z;
    const float* W    = (mat == 0) ? Wz : ((mat == 1) ? Wr : Wh);
    const float* bias = (mat == 0) ? bz : ((mat == 1) ? br : bh);
    float* dst = &g_x[mat][0];

    const int m0 = blockIdx.y * 128;
    const int n0 = blockIdx.x * 64;
    const int tid = threadIdx.x;
    const int tx = tid & 15;        // n-group (4 cols)
    const int ty = tid >> 4;        // m-group (8 rows)

    float acc[8][4];
#pragma unroll
    for (int i = 0; i < 8; ++i)
#pragma unroll
        for (int j = 0; j < 4; ++j) acc[i][j] = 0.f;

    for (int kt = 0; kt < 512; kt += 16) {
#pragma unroll
        for (int ii = 0; ii < 2; ++ii) {
            int i = tid + ii * 256;            // 0..511 (float4 index)
            int r = i >> 2;                    // row in tile 0..127
            int cq = i & 3;                    // which float4 in the 16-k row
            float4 v = *(const float4*)&X[(m0 + r) * 512 + kt + cq * 4];
            As[(cq * 4 + 0) * 132 + r] = v.x;
            As[(cq * 4 + 1) * 132 + r] = v.y;
            As[(cq * 4 + 2) * 132 + r] = v.z;
            As[(cq * 4 + 3) * 132 + r] = v.w;
        }
        {
            int r = tid >> 4;                  // k row 0..15
            int c = (tid & 15) * 4;            // col
            float4 v = *(const float4*)&W[(kt + r) * 512 + n0 + c];
            *(float4*)&Bs[r * 68 + c] = v;
        }
        __syncthreads();
#pragma unroll
        for (int k = 0; k < 16; ++k) {
            float4 a0 = *(const float4*)&As[k * 132 + ty * 8];
            float4 a1 = *(const float4*)&As[k * 132 + ty * 8 + 4];
            float4 bv = *(const float4*)&Bs[k * 68 + tx * 4];
            float a[8] = {a0.x, a0.y, a0.z, a0.w, a1.x, a1.y, a1.z, a1.w};
            float bb[4] = {bv.x, bv.y, bv.z, bv.w};
#pragma unroll
            for (int im = 0; im < 8; ++im)
#pragma unroll
                for (int ij = 0; ij < 4; ++ij)
                    acc[im][ij] = fmaf(a[im], bb[ij], acc[im][ij]);
        }
        __syncthreads();
    }

    float4 bv = *(const float4*)&bias[n0 + tx * 4];
#pragma unroll
    for (int im = 0; im < 8; ++im) {
        int m = m0 + ty * 8 + im;
        int t = m & 511;         // X is [B,T,D]: m = b*T + t
        int b = m >> 9;
        float4 o;
        o.x = acc[im][0] + bv.x;
        o.y = acc[im][1] + bv.y;
        o.z = acc[im][2] + bv.z;
        o.w = acc[im][3] + bv.w;
        *(float4*)&dst[(t * 64 + b) * 512 + n0 + tx * 4] = o;  // time-major [t][b][j]
    }
}

// =================================================================
// Phase 2: persistent GRU recurrence. 128 blocks x 256 threads.
// State kept j-major in global (g_hT/g_rhT/g_zT) so staging into the
// transposed smem compute layout is a conflict-free coalesced copy.
// =================================================================
// smem floats: h_s 512*68 + Ua 512*8 + Ub 512*4 + red 256*20 + mask 64
#define SMEM_FLOATS (512*68 + 512*8 + 512*4 + 256*20 + 64)

__global__ __launch_bounds__(256) void gru_kernel(
    const float* __restrict__ Uz, const float* __restrict__ Ur, const float* __restrict__ Uh,
    const int* __restrict__ mask, float* __restrict__ out)
{
    extern __shared__ float sm[];
    float* h_s  = sm;                       // [512][68] transposed state (h or r*h)
    float* Ua_s = sm + 512 * 68;            // [512][8]  U_z or U_r slice (persistent)
    float* Ub_s = Ua_s + 512 * 8;           // [512][4]  U_h slice (persistent)
    float* red  = Ub_s + 512 * 4;           // [256][20] split-K reduction (padded)
    int*   m_si = (int*)(red + 256 * 20);   // [64] mask for this timestep

    const int tid  = threadIdx.x;
    const int jblk = blockIdx.x;            // 0..127
    const bool isZ = (jblk < 64);
    const int jbase8 = (isZ ? jblk : jblk - 64) * 8;  // z|r column base
    const int jbase4 = jblk * 4;                      // U_h column base

    // ---- stage U slices once (constant across all 512 steps) ----
    {
        const float* Usel = isZ ? Uz : Ur;
        for (int i = tid; i < 1024; i += 256) {       // 512 rows x 2 float4
            int r = i >> 1, c = (i & 1) * 4;
            float4 v = *(const float4*)&Usel[r * 512 + jbase8 + c];
            *(float4*)&Ua_s[r * 8 + c] = v;
        }
        for (int i = tid; i < 512; i += 256) {
            float4 v = *(const float4*)&Uh[i * 512 + jbase4];
            *(float4*)&Ub_s[i * 4] = v;
        }
    }

    // ---- zero h (128*256 threads == 32768 elements, exactly one each) ----
    g_hT[jblk * 256 + tid] = 0.f;

    unsigned int barno = 0;
    grid_barrier(++barno * 128u);

    const int kc = tid >> 5;                // warp id = K chunk (64 k each)
    const int jg = (tid >> 4) & 1;
    const int bg = tid & 15;
    const int b0 = bg * 4;
    const int k0 = kc * 64;
    const int jg4 = jg * 4;
    const int jg2 = jg * 2;

    for (int t = 0; t < TLEN; ++t) {
        // =================== Phase A: z and r ===================
        // stage hT: coalesced float4 copy, conflict-free STS
#pragma unroll 4
        for (int i = tid; i < 8192; i += 256) {
            int j = i >> 4, bq = (i & 15) << 2;
            float4 v = __ldcg((const float4*)(g_hT + j * 64 + bq));
            *(float4*)&h_s[j * 68 + bq] = v;
        }
        __syncthreads();

        float acc[4][4];
#pragma unroll
        for (int i = 0; i < 4; ++i)
#pragma unroll
            for (int j = 0; j < 4; ++j) acc[i][j] = 0.f;

#pragma unroll 4
        for (int k = k0; k < k0 + 64; ++k) {
            float4 hv = *(const float4*)(h_s + k * 68 + b0);
            float4 uv = *(const float4*)(Ua_s + k * 8 + jg4);
            float a[4] = {hv.x, hv.y, hv.z, hv.w};
            float u[4] = {uv.x, uv.y, uv.z, uv.w};
#pragma unroll
            for (int ib = 0; ib < 4; ++ib)
#pragma unroll
                for (int ij = 0; ij < 4; ++ij)
                    acc[ib][ij] = fmaf(a[ib], u[ij], acc[ib][ij]);
        }

#pragma unroll
        for (int ib = 0; ib < 4; ++ib)
#pragma unroll
            for (int ij = 0; ij < 4; ++ij)
                red[tid * 20 + ib * 4 + ij] = acc[ib][ij];
        __syncthreads();

        {
            const float* xarr = isZ ? &g_x[0][0] : &g_x[1][0];
#pragma unroll
            for (int q = 0; q < 2; ++q) {
                int o = tid + q * 256;          // 512 outputs: jl fast, b slow
                int jl = o & 7, b = o >> 3;
                int bgr = b >> 2, ibr = b & 3, jgr = jl >> 2, ijr = jl & 3;
                float s = 0.f;
#pragma unroll
                for (int c = 0; c < 8; ++c)
                    s += red[(c * 32 + jgr * 16 + bgr) * 20 + ibr * 4 + ijr];
                int j = jbase8 + jl;
                float v = xarr[t * 32768 + b * 512 + j] + s;
                float sg = 1.f / (1.f + __expf(-v));
                if (isZ) g_zT[j * 64 + b] = sg;
                else     g_rhT[j * 64 + b] = sg * h_s[j * 68 + b];
            }
        }
        grid_barrier(++barno * 128u);

        // =================== Phase B: candidate + update ===================
#pragma unroll 4
        for (int i = tid; i < 8192; i += 256) {
            int j = i >> 4, bq = (i & 15) << 2;
            float4 v = __ldcg((const float4*)(g_rhT + j * 64 + bq));
            *(float4*)&h_s[j * 68 + bq] = v;
        }
        if (tid < 64) m_si[tid] = mask[tid * 512 + t];
        __syncthreads();

        float acc2[4][2];
#pragma unroll
        for (int i = 0; i < 4; ++i) { acc2[i][0] = 0.f; acc2[i][1] = 0.f; }

#pragma unroll 4
        for (int k = k0; k < k0 + 64; ++k) {
            float4 hv = *(const float4*)(h_s + k * 68 + b0);
            float2 uv = *(const float2*)(Ub_s + k * 4 + jg2);
            float a[4] = {hv.x, hv.y, hv.z, hv.w};
#pragma unroll
            for (int ib = 0; ib < 4; ++ib) {
                acc2[ib][0] = fmaf(a[ib], uv.x, acc2[ib][0]);
                acc2[ib][1] = fmaf(a[ib], uv.y, acc2[ib][1]);
            }
        }

#pragma unroll
        for (int ib = 0; ib < 4; ++ib) {
            red[tid * 20 + ib * 2 + 0] = acc2[ib][0];
            red[tid * 20 + ib * 2 + 1] = acc2[ib][1];
        }
        __syncthreads();

        {
            int o = tid;                        // 256 outputs: b fast, jl slow
            int b = o & 63, jl = o >> 6;        // jl 0..3
            int bgr = b >> 2, ibr = b & 3;
            float s = 0.f;
#pragma unroll
            for (int c = 0; c < 8; ++c)
                s += red[(c * 32 + (jl >> 1) * 16 + bgr) * 20 + ibr * 2 + (jl & 1)];
            int j = jbase4 + jl;
            float hh   = tanhf(g_x[2][t * 32768 + b * 512 + j] + s);
            float z    = __ldcg(g_zT + j * 64 + b);
            float hold = __ldcg(g_hT + j * 64 + b);
            float hn   = z * hold + (1.f - z) * hh;
            float res  = (m_si[b] > 0) ? hn : hold;
            g_hT[j * 64 + b] = res;
            if (t == TLEN - 1) out[b * 512 + j] = res;
        }
        grid_barrier(++barno * 128u);
    }
}

// =================================================================
extern "C" void kernel_launch(void* const* d_in, const int* in_sizes, int n_in,
                              void* d_out, int out_size) {
    (void)in_sizes; (void)n_in; (void)out_size;
    const float* X    = (const float*)d_in[0];
    const int*   mask = (const int*)  d_in[1];
    const float* Wz   = (const float*)d_in[2];
    const float* Uz   = (const float*)d_in[3];
    const float* bz   = (const float*)d_in[4];
    const float* Wr   = (const float*)d_in[5];
    const float* Ur   = (const float*)d_in[6];
    const float* br   = (const float*)d_in[7];
    const float* Wh   = (const float*)d_in[8];
    const float* Uh   = (const float*)d_in[9];
    const float* bh   = (const float*)d_in[10];
    float* out = (float*)d_out;

    const int smem_bytes = SMEM_FLOATS * (int)sizeof(float);
    cudaFuncSetAttribute(gru_kernel, cudaFuncAttributeMaxDynamicSharedMemorySize, smem_bytes);

    proj_kernel<<<dim3(8, 256, 3), 256>>>(X, Wz, Wr, Wh, bz, br, bh);
    gru_kernel<<<128, 256, smem_bytes>>>(Uz, Ur, Uh, mask, out);
}

// round 5
// speedup vs baseline: 2.5611x; 1.5330x over previous
#include <cuda_runtime.h>
#include <cuda_bf16.h>
#include <math.h>

#define BATCH 64
#define TLEN  512
#define DIM   512

// Grid decomposition: 4 batch-groups x 32 col-groups = 128 blocks.
// Block owns 16 batches x 16 columns of each gate (z, r, h aligned).
#define NGRP   4
#define GBLKS  32      // blocks per group
#define BPG    16      // batches per group/block
#define CPB    16      // columns per gate per block

// -------- device scratch --------
__device__ float g_x[3][TLEN * BATCH * DIM];   // [gate][t][b][j]
__device__ float g_h[DIM * BATCH];             // [j][b]  (b fast, 64 wide)
__device__ float g_rh[DIM * BATCH];            // [j][b]
__device__ unsigned int g_cnt[NGRP * 32];      // one counter per group, 128B apart

// =================================================================
// Phase 1: input projections (unchanged from R3; ~1.9ms)
// =================================================================
__global__ __launch_bounds__(256) void proj_kernel(
    const float* __restrict__ X,
    const float* __restrict__ Wz, const float* __restrict__ Wr, const float* __restrict__ Wh,
    const float* __restrict__ bz, const float* __restrict__ br, const float* __restrict__ bh)
{
    __shared__ float As[16 * 132];
    __shared__ float Bs[16 * 68];

    if (blockIdx.x == 0 && blockIdx.y == 0 && blockIdx.z == 0 && threadIdx.x < NGRP * 32)
        g_cnt[threadIdx.x] = 0u;

    const int mat = blockIdx.z;
    const float* W    = (mat == 0) ? Wz : ((mat == 1) ? Wr : Wh);
    const float* bias = (mat == 0) ? bz : ((mat == 1) ? br : bh);
    float* dst = &g_x[mat][0];

    const int m0 = blockIdx.y * 128;
    const int n0 = blockIdx.x * 64;
    const int tid = threadIdx.x;
    const int tx = tid & 15;
    const int ty = tid >> 4;

    float acc[8][4];
#pragma unroll
    for (int i = 0; i < 8; ++i)
#pragma unroll
        for (int j = 0; j < 4; ++j) acc[i][j] = 0.f;

    for (int kt = 0; kt < 512; kt += 16) {
#pragma unroll
        for (int ii = 0; ii < 2; ++ii) {
            int i = tid + ii * 256;
            int r = i >> 2;
            int cq = i & 3;
            float4 v = *(const float4*)&X[(m0 + r) * 512 + kt + cq * 4];
            As[(cq * 4 + 0) * 132 + r] = v.x;
            As[(cq * 4 + 1) * 132 + r] = v.y;
            As[(cq * 4 + 2) * 132 + r] = v.z;
            As[(cq * 4 + 3) * 132 + r] = v.w;
        }
        {
            int r = tid >> 4;
            int c = (tid & 15) * 4;
            float4 v = *(const float4*)&W[(kt + r) * 512 + n0 + c];
            *(float4*)&Bs[r * 68 + c] = v;
        }
        __syncthreads();
#pragma unroll
        for (int k = 0; k < 16; ++k) {
            float4 a0 = *(const float4*)&As[k * 132 + ty * 8];
            float4 a1 = *(const float4*)&As[k * 132 + ty * 8 + 4];
            float4 bv = *(const float4*)&Bs[k * 68 + tx * 4];
            float a[8] = {a0.x, a0.y, a0.z, a0.w, a1.x, a1.y, a1.z, a1.w};
            float bb[4] = {bv.x, bv.y, bv.z, bv.w};
#pragma unroll
            for (int im = 0; im < 8; ++im)
#pragma unroll
                for (int ij = 0; ij < 4; ++ij)
                    acc[im][ij] = fmaf(a[im], bb[ij], acc[im][ij]);
        }
        __syncthreads();
    }

    float4 bv = *(const float4*)&bias[n0 + tx * 4];
#pragma unroll
    for (int im = 0; im < 8; ++im) {
        int m = m0 + ty * 8 + im;
        int t = m & 511;
        int b = m >> 9;
        float4 o;
        o.x = acc[im][0] + bv.x;
        o.y = acc[im][1] + bv.y;
        o.z = acc[im][2] + bv.z;
        o.w = acc[im][3] + bv.w;
        *(float4*)&dst[(t * 64 + b) * 512 + n0 + tx * 4] = o;  // [t][b][j]
    }
}

// =================================================================
// Phase 2: persistent GRU, 128 blocks (4 indep groups of 32) x 256 thr
// =================================================================
// smem floats: h_s 512*16 + rh_s 512*16 + Uzr 512*36 + Uh 512*18
//            + red 16*16*37 + z_s 16*17 + mask pad
#define SM_HS   (512*16)
#define SM_RHS  (512*16)
#define SM_UZR  (512*36)
#define SM_UH   (512*18)
#define SM_RED  (16*16*37)
#define SM_ZS   (16*16)
#define SMEM_FLOATS (SM_HS + SM_RHS + SM_UZR + SM_UH + SM_RED + SM_ZS + 32)

__device__ __forceinline__ void group_barrier(unsigned int* cnt, unsigned int target) {
    __threadfence();
    __syncthreads();
    if (threadIdx.x == 0) {
        atomicAdd(cnt, 1u);
        while (*((volatile unsigned int*)cnt) < target) { }
    }
    __syncthreads();
}

__global__ __launch_bounds__(256) void gru_kernel(
    const float* __restrict__ Uz, const float* __restrict__ Ur, const float* __restrict__ Uh,
    const int* __restrict__ mask, float* __restrict__ out)
{
    extern __shared__ float sm[];
    float* h_s   = sm;                       // [512][16] h_old (all j, block batches)
    float* rh_s  = h_s + SM_HS;              // [512][16] r*h
    float* Uzr_s = rh_s + SM_RHS;            // [512][36] cols 0-15=z, 16-31=r
    float* Uh_s  = Uzr_s + SM_UZR;           // [512][18] cols 0-15
    float* red   = Uh_s + SM_UH;             // [256][37] split-K partials
    float* z_s   = red + SM_RED;             // [16 cols][16 b]
    int*   m_s   = (int*)(z_s + SM_ZS);      // [16]

    const int tid = threadIdx.x;
    const int bx  = blockIdx.x;
    const int bg  = bx >> 5;                 // batch group 0..3
    const int jg  = bx & 31;                 // col group 0..31
    const int jb  = jg * CPB;                // global column base (per gate)
    const int b_base = bg * BPG;             // global batch base
    unsigned int* cnt = &g_cnt[bg * 32];

    // ---- stage U slices once ----
    for (int i = tid; i < 512 * 16; i += 256) {
        int k = i >> 4, c = i & 15;
        Uzr_s[k * 36 + c]      = Uz[k * 512 + jb + c];
        Uzr_s[k * 36 + 16 + c] = Ur[k * 512 + jb + c];
        Uh_s [k * 18 + c]      = Uh[k * 512 + jb + c];
    }

    // ---- zero h: 128*256 = 32768 elements exactly ----
    g_h[bx * 256 + tid] = 0.f;

    unsigned int round = 0;
    group_barrier(cnt, ++round * GBLKS);

    // compute decomposition
    const int chunk = tid >> 4;              // 16 k-chunks, k = chunk + 16*s
    const int sub   = tid & 15;
    const int bt    = sub >> 3;              // 0..1
    const int b0    = bt * 8;
    const int ctA   = sub & 7;               // 8 col-tiles of 4 (z|r combined)
    const int c0A   = ctA * 4;
    const int c0B   = (sub & 7) * 2;         // phase B: 8 tiles of 2 cols

    // epilogue mapping
    const int bl0  = tid & 15;               // batch (b fast -> coalesced writes)
    const int cz   = tid >> 4;               // column 0..15
    const int btE  = bl0 >> 3;
    const int bhat = bl0 & 7;

    for (int t = 0; t < TLEN; ++t) {
        // =================== Phase A: z and r ===================
        // prefetch projections (fly during staging + compute)
        float xz = g_x[0][t * 32768 + (b_base + bl0) * 512 + jb + cz];
        float xr = g_x[1][t * 32768 + (b_base + bl0) * 512 + jb + cz];
        // stage h (16 batches, all 512 j): 2048 float4
#pragma unroll 2
        for (int i = tid; i < 2048; i += 256) {
            int j = i >> 2, bq = (i & 3) << 2;
            float4 v = __ldcg((const float4*)(g_h + j * 64 + b_base + bq));
            *(float4*)&h_s[j * 16 + bq] = v;
        }
        __syncthreads();

        float acc[8][4];
#pragma unroll
        for (int i = 0; i < 8; ++i)
#pragma unroll
            for (int j = 0; j < 4; ++j) acc[i][j] = 0.f;

#pragma unroll 4
        for (int s = 0; s < 32; ++s) {
            int k = chunk + (s << 4);
            float4 h0 = *(const float4*)&h_s[k * 16 + b0];
            float4 h1 = *(const float4*)&h_s[k * 16 + b0 + 4];
            float4 uv = *(const float4*)&Uzr_s[k * 36 + c0A];
            float hv[8] = {h0.x, h0.y, h0.z, h0.w, h1.x, h1.y, h1.z, h1.w};
            float uu[4] = {uv.x, uv.y, uv.z, uv.w};
#pragma unroll
            for (int ib = 0; ib < 8; ++ib)
#pragma unroll
                for (int ic = 0; ic < 4; ++ic)
                    acc[ib][ic] = fmaf(hv[ib], uu[ic], acc[ib][ic]);
        }

        {
            int slot = (chunk * 16 + sub) * 37;
#pragma unroll
            for (int ib = 0; ib < 8; ++ib)
#pragma unroll
                for (int ic = 0; ic < 4; ++ic)
                    red[slot + ib * 4 + ic] = acc[ib][ic];
        }
        __syncthreads();

        {
            float s0 = 0.f, s1 = 0.f;
#pragma unroll
            for (int c = 0; c < 16; ++c) {
                s0 += red[(c * 16 + btE * 8 + (cz >> 2)) * 37 + bhat * 4 + (cz & 3)];
                s1 += red[(c * 16 + btE * 8 + 4 + (cz >> 2)) * 37 + bhat * 4 + (cz & 3)];
            }
            float zg = 1.f / (1.f + __expf(-(xz + s0)));
            z_s[cz * 16 + bl0] = zg;
            int jglob = jb + cz;
            float rg = 1.f / (1.f + __expf(-(xr + s1)));
            g_rh[jglob * 64 + b_base + bl0] = rg * h_s[jglob * 16 + bl0];
        }
        group_barrier(cnt, ++round * GBLKS);

        // =================== Phase B: candidate + update ===================
        float xh = g_x[2][t * 32768 + (b_base + bl0) * 512 + jb + cz];
#pragma unroll 2
        for (int i = tid; i < 2048; i += 256) {
            int j = i >> 2, bq = (i & 3) << 2;
            float4 v = __ldcg((const float4*)(g_rh + j * 64 + b_base + bq));
            *(float4*)&rh_s[j * 16 + bq] = v;
        }
        if (tid < 16) m_s[tid] = mask[(b_base + tid) * 512 + t];
        __syncthreads();

        float acc2[8][2];
#pragma unroll
        for (int i = 0; i < 8; ++i) { acc2[i][0] = 0.f; acc2[i][1] = 0.f; }

#pragma unroll 4
        for (int s = 0; s < 32; ++s) {
            int k = chunk + (s << 4);
            float4 r0 = *(const float4*)&rh_s[k * 16 + b0];
            float4 r1 = *(const float4*)&rh_s[k * 16 + b0 + 4];
            float2 uv = *(const float2*)&Uh_s[k * 18 + c0B];
            float rv[8] = {r0.x, r0.y, r0.z, r0.w, r1.x, r1.y, r1.z, r1.w};
#pragma unroll
            for (int ib = 0; ib < 8; ++ib) {
                acc2[ib][0] = fmaf(rv[ib], uv.x, acc2[ib][0]);
                acc2[ib][1] = fmaf(rv[ib], uv.y, acc2[ib][1]);
            }
        }

        {
            int slot = (chunk * 16 + sub) * 37;
#pragma unroll
            for (int ib = 0; ib < 8; ++ib) {
                red[slot + ib * 4 + 0] = acc2[ib][0];
                red[slot + ib * 4 + 1] = acc2[ib][1];
            }
        }
        __syncthreads();

        {
            float s2 = 0.f;
#pragma unroll
            for (int c = 0; c < 16; ++c)
                s2 += red[(c * 16 + btE * 8 + (cz >> 1)) * 37 + bhat * 4 + (cz & 1)];
            float hh = tanhf(xh + s2);
            float zg = z_s[cz * 16 + bl0];
            int jglob = jb + cz;
            float hold = h_s[jglob * 16 + bl0];
            float hn   = zg * hold + (1.f - zg) * hh;
            float res  = (m_s[bl0] > 0) ? hn : hold;
            g_h[jglob * 64 + b_base + bl0] = res;
            if (t == TLEN - 1) out[(b_base + bl0) * 512 + jglob] = res;
        }
        group_barrier(cnt, ++round * GBLKS);
    }
}

// =================================================================
extern "C" void kernel_launch(void* const* d_in, const int* in_sizes, int n_in,
                              void* d_out, int out_size) {
    (void)in_sizes; (void)n_in; (void)out_size;
    const float* X    = (const float*)d_in[0];
    const int*   mask = (const int*)  d_in[1];
    const float* Wz   = (const float*)d_in[2];
    const float* Uz   = (const float*)d_in[3];
    const float* bz   = (const float*)d_in[4];
    const float* Wr   = (const float*)d_in[5];
    const float* Ur   = (const float*)d_in[6];
    const float* br   = (const float*)d_in[7];
    const float* Wh   = (const float*)d_in[8];
    const float* Uh   = (const float*)d_in[9];
    const float* bh   = (const float*)d_in[10];
    float* out = (float*)d_out;

    const int smem_bytes = SMEM_FLOATS * (int)sizeof(float);   // ~215 KB
    cudaFuncSetAttribute(gru_kernel, cudaFuncAttributeMaxDynamicSharedMemorySize, smem_bytes);

    proj_kernel<<<dim3(8, 256, 3), 256>>>(X, Wz, Wr, Wh, bz, br, bh);
    gru_kernel<<<128, 256, smem_bytes>>>(Uz, Ur, Uh, mask, out);
}